// round 3
// baseline (speedup 1.0000x reference)
#include <cuda_runtime.h>
#include <math.h>

// Problem dims
#define NB   32            // batch
#define NT   512           // seq len
#define ND   1024          // input size
#define NH   1024          // hidden size
#define NG   4096          // 4*H
#define MTOT (NB * NT)     // 16384 rows of x_proj

// Scratch (allocation-free rule: __device__ globals)
__device__ float g_xproj[(size_t)MTOT * NG];   // 256 MB
__device__ float g_c[NB * NH];                 // cell state, 128 KB

// ---------------------------------------------------------------------------
// f32x2 packed-FMA helpers (sm_103a FFMA2 — only reachable via PTX)
// ---------------------------------------------------------------------------
__device__ __forceinline__ unsigned long long pack2(float lo, float hi) {
    unsigned long long r;
    asm("mov.b64 %0, {%1, %2};" : "=l"(r) : "f"(lo), "f"(hi));
    return r;
}
__device__ __forceinline__ void ffma2(unsigned long long& d,
                                      unsigned long long a,
                                      unsigned long long b) {
    asm("fma.rn.f32x2 %0, %1, %2, %0;" : "+l"(d) : "l"(a), "l"(b));
}
__device__ __forceinline__ float2 unpack2(unsigned long long v) {
    float2 f;
    asm("mov.b64 {%0, %1}, %2;" : "=f"(f.x), "=f"(f.y) : "l"(v));
    return f;
}

__device__ __forceinline__ float sigmoidf_(float x) {
    return 1.0f / (1.0f + __expf(-x));
}
__device__ __forceinline__ float tanh_fast(float x) {
    float a = fabsf(x);
    float e = __expf(-2.0f * a);
    float r = (1.0f - e) / (1.0f + e);
    return copysignf(r, x);
}

// ---------------------------------------------------------------------------
// init: zero cell state (graph replays restart from t=0)
// ---------------------------------------------------------------------------
__global__ void init_c_kernel() {
    int i = blockIdx.x * blockDim.x + threadIdx.x;
    if (i < NB * NH) g_c[i] = 0.0f;
}

// ---------------------------------------------------------------------------
// x_proj = x @ W_ih + bias    (M=16384, N=4096, K=1024)
// 128x128x8 tiled SGEMM, 256 threads, 8x8 register tiles via FFMA2.
// ---------------------------------------------------------------------------
__global__ __launch_bounds__(256) void sgemm_xproj(const float* __restrict__ A,
                                                   const float* __restrict__ Bm,
                                                   const float* __restrict__ bias) {
    __shared__ __align__(16) float As[8 * 128];
    __shared__ __align__(16) float Bs[8 * 128];

    const int tid = threadIdx.x;
    const int rowBase = blockIdx.y * 128;
    const int colBase = blockIdx.x * 128;

    const int irA = tid >> 1;          // 0..127
    const int icA = (tid & 1) * 4;     // 0 or 4
    const int irB = tid >> 5;          // 0..7
    const int icB = (tid & 31) * 4;    // 0..124

    const int trow = tid >> 4;         // 0..15
    const int tcol = tid & 15;         // 0..15

    unsigned long long res2[8][4];
#pragma unroll
    for (int i = 0; i < 8; i++)
#pragma unroll
        for (int j = 0; j < 4; j++) res2[i][j] = 0ull;   // bits of (0.f,0.f)

    for (int bk = 0; bk < ND; bk += 8) {
        float4 a = *(const float4*)&A[(size_t)(rowBase + irA) * ND + bk + icA];
        As[(icA + 0) * 128 + irA] = a.x;
        As[(icA + 1) * 128 + irA] = a.y;
        As[(icA + 2) * 128 + irA] = a.z;
        As[(icA + 3) * 128 + irA] = a.w;
        *(float4*)&Bs[irB * 128 + icB] =
            *(const float4*)&Bm[(size_t)(bk + irB) * NG + colBase + icB];
        __syncthreads();

#pragma unroll
        for (int kk = 0; kk < 8; kk++) {
            float regM[8];
            *(float4*)&regM[0] = *(float4*)&As[kk * 128 + trow * 8];
            *(float4*)&regM[4] = *(float4*)&As[kk * 128 + trow * 8 + 4];
            ulonglong2 n01 = *(const ulonglong2*)&Bs[kk * 128 + tcol * 8];
            ulonglong2 n23 = *(const ulonglong2*)&Bs[kk * 128 + tcol * 8 + 4];
#pragma unroll
            for (int i = 0; i < 8; i++) {
                unsigned long long mm = pack2(regM[i], regM[i]);
                ffma2(res2[i][0], mm, n01.x);
                ffma2(res2[i][1], mm, n01.y);
                ffma2(res2[i][2], mm, n23.x);
                ffma2(res2[i][3], mm, n23.y);
            }
        }
        __syncthreads();
    }

#pragma unroll
    for (int i = 0; i < 8; i++) {
#pragma unroll
        for (int jp = 0; jp < 4; jp += 2) {
            int col = colBase + tcol * 8 + jp * 2;
            float2 v0 = unpack2(res2[i][jp]);
            float2 v1 = unpack2(res2[i][jp + 1]);
            float4 o;
            o.x = v0.x + bias[col + 0];
            o.y = v0.y + bias[col + 1];
            o.z = v1.x + bias[col + 2];
            o.w = v1.y + bias[col + 3];
            *(float4*)&g_xproj[(size_t)(rowBase + trow * 8 + i) * NG + col] = o;
        }
    }
}

// ---------------------------------------------------------------------------
// One LSTM timestep.
// Grid: 128 CTAs x 512 threads. CTA owns 8 h-cols (base..base+7) => 32 gate
// columns (i,f,g,o x 8). 16 warps: warp w -> K-slice ks=w>>1 (128 of K),
// col-half ch=w&1 (16 cols). lane = batch.
// Inner loop per k: 1 LDS (h, conflict-free), 4 broadcast LDS.128 (W),
// 1 pack, 8 FFMA2 -> 8x2=16 MACs/lane/k.
// K staged in 16 double-buffered chunks of 64. Partials reduced via smem,
// fused gate/c/h update. h_{t-1} read from the output tensor.
// ---------------------------------------------------------------------------
__global__ __launch_bounds__(512) void lstm_step(const float* __restrict__ Whh,
                                                 float* __restrict__ out, int t) {
    // Hs: 2 x [32][65] = 4160 floats, Ws: 2 x [64][32] = 4096 floats.
    // red: [8][32*33] = 8448 floats, aliases the whole array after final sync.
    __shared__ __align__(16) float sm[8448];
    float* Hs = sm;              // 2 x 2080
    float* Ws = sm + 4160;       // 2 x 2048

    const int tid  = threadIdx.x;
    const int base = blockIdx.x * 8;
    const int wid  = tid >> 5;       // 0..15
    const int lane = tid & 31;       // batch
    const int ks   = wid >> 1;       // 0..7  K-split
    const int ch   = wid & 1;        // col half

    unsigned long long acc[8];
#pragma unroll
    for (int j = 0; j < 8; j++) acc[j] = 0ull;

    if (t > 0) {
        const size_t hrow = (size_t)NT * NH;
        const size_t hoff = (size_t)(t - 1) * NH;

        // staging index decode (512 threads, chunk = 64 k)
        const int hl = tid & 31;         // batch row for h load
        const int hm = tid >> 5;         // float4 index 0..15 within 64-k chunk
        const int wkl = tid >> 3;        // 0..63  k within chunk for W load
        const int wc4 = tid & 7;         // col quad 0..7
        const int wg  = wc4 >> 1;        // gate
        const int wjq = (wc4 & 1) * 4;   // jj quad

        float4 hr, wr;

#define LDG_CHUNK(c)                                                            \
        {                                                                       \
            const int kb = (c) * 64;                                            \
            hr = *(const float4*)&out[(size_t)hl * hrow + hoff + kb + hm * 4];  \
            wr = *(const float4*)&Whh[(size_t)(kb + wkl) * NG + wg * 1024 +     \
                                      base + wjq];                              \
        }

#define STS_CHUNK(bf)                                                           \
        {                                                                       \
            float* hb = Hs + (bf) * 2080;                                       \
            float* wb = Ws + (bf) * 2048;                                       \
            hb[hl * 65 + hm * 4 + 0] = hr.x;                                    \
            hb[hl * 65 + hm * 4 + 1] = hr.y;                                    \
            hb[hl * 65 + hm * 4 + 2] = hr.z;                                    \
            hb[hl * 65 + hm * 4 + 3] = hr.w;                                    \
            *(float4*)&wb[wkl * 32 + wc4 * 4] = wr;                             \
        }

        LDG_CHUNK(0);
        STS_CHUNK(0);
        __syncthreads();

        for (int c = 0; c < 16; c++) {
            if (c < 15) LDG_CHUNK(c + 1);

            const int bf = c & 1;
            const float* hb = Hs + bf * 2080 + lane * 65 + ks * 8;
            const float* wb = Ws + bf * 2048 + ch * 16 + ks * 8 * 32;

#pragma unroll
            for (int kk = 0; kk < 8; kk++) {
                float h = hb[kk];
                unsigned long long hh = pack2(h, h);
                const float* wrow = wb + kk * 32;
                ulonglong2 wA = *(const ulonglong2*)(wrow);
                ulonglong2 wB = *(const ulonglong2*)(wrow + 4);
                ulonglong2 wC = *(const ulonglong2*)(wrow + 8);
                ulonglong2 wD = *(const ulonglong2*)(wrow + 12);
                ffma2(acc[0], hh, wA.x);
                ffma2(acc[1], hh, wA.y);
                ffma2(acc[2], hh, wB.x);
                ffma2(acc[3], hh, wB.y);
                ffma2(acc[4], hh, wC.x);
                ffma2(acc[5], hh, wC.y);
                ffma2(acc[6], hh, wD.x);
                ffma2(acc[7], hh, wD.y);
            }

            if (c < 15) STS_CHUNK((c + 1) & 1);
            __syncthreads();
        }
#undef LDG_CHUNK
#undef STS_CHUNK
    }

    // write K-split partials (red aliases Hs/Ws; all compute synced above)
    float* red = sm;   // [8][32*33]
    {
        float* r = red + ks * 1056 + lane * 33 + ch * 16;
#pragma unroll
        for (int j = 0; j < 8; j++) {
            float2 v = unpack2(acc[j]);
            r[2 * j + 0] = v.x;
            r[2 * j + 1] = v.y;
        }
    }
    __syncthreads();

    // fused gate nonlinearity + c/h update; thread owns (b, jj)
    if (tid < 256) {
        const int b  = tid >> 3;     // 0..31
        const int jj = tid & 7;      // 0..7
        float gate[4];
#pragma unroll
        for (int g = 0; g < 4; g++) {
            const int col = g * 8 + jj;
            float s = 0.0f;
#pragma unroll
            for (int kv = 0; kv < 8; kv++) s += red[kv * 1056 + b * 33 + col];
            s += g_xproj[((size_t)b * NT + t) * NG + g * 1024 + base + jj];
            gate[g] = s;
        }
        const float ig = sigmoidf_(gate[0]);
        const float fg = sigmoidf_(gate[1]);
        const float gg = tanh_fast(gate[2]);
        const float og = sigmoidf_(gate[3]);

        const int ci = b * NH + base + jj;
        const float c = fg * g_c[ci] + ig * gg;
        g_c[ci] = c;
        out[((size_t)b * NT + t) * NH + base + jj] = og * tanh_fast(c);
    }
}

// ---------------------------------------------------------------------------
// finalize: append h_T and c_T after hidden_seq (flattened pytree order:
// hidden_seq, h_T, c_T)
// ---------------------------------------------------------------------------
__global__ void finalize_kernel(float* __restrict__ out) {
    int i = blockIdx.x * blockDim.x + threadIdx.x;
    if (i < NB * NH) {
        const size_t HS = (size_t)NB * NT * NH;
        int b = i >> 10;
        int k = i & 1023;
        out[HS + i] = out[((size_t)b * NT + (NT - 1)) * NH + k];
        out[HS + NB * NH + i] = g_c[i];
    }
}

// ---------------------------------------------------------------------------
// launch
// ---------------------------------------------------------------------------
extern "C" void kernel_launch(void* const* d_in, const int* in_sizes, int n_in,
                              void* d_out, int out_size) {
    const float* x    = (const float*)d_in[0];
    const float* wih  = (const float*)d_in[1];
    const float* whh  = (const float*)d_in[2];
    const float* bias = (const float*)d_in[3];
    float* out = (float*)d_out;

    (void)in_sizes; (void)n_in;

    init_c_kernel<<<(NB * NH + 255) / 256, 256>>>();

    {
        dim3 grid(NG / 128, MTOT / 128);   // (32, 128)
        sgemm_xproj<<<grid, 256>>>(x, wih, bias);
    }

    for (int t = 0; t < NT; t++) {
        lstm_step<<<NH / 8, 512>>>(whh, out, t);
    }

    if (out_size >= NB * NT * NH + 2 * NB * NH) {
        finalize_kernel<<<(NB * NH + 255) / 256, 256>>>(out);
    }
}

// round 5
// speedup vs baseline: 1.5390x; 1.5390x over previous
#include <cuda_runtime.h>
#include <math.h>

// Problem dims
#define NB   32
#define NT   512
#define ND   1024
#define NH   1024
#define NG   4096
#define MTOT (NB * NT)
#define NCTA 128
#define NTHR 512
#define HSEQ ((size_t)NB * NT * NH)

// Scratch (allocation-free rule: __device__ globals)
__device__ float g_xproj[(size_t)MTOT * NG];   // 256 MB
__device__ unsigned g_barrier;

// smem float offsets (persistent kernel)
#define WS_F  0                      // W slice: 1024 x 32            = 32768 fl
#define XB_F  32768                  // xbuf: 32 x 36                 = 1152 fl
#define GB_F  (32768 + 1152)         // gbuf: 32 cols x 17 u64        = 1088 fl
#define SCR_F (GB_F + 1088)          // scratch: max(red 16K, Hs 4608)= 16384 fl
#define SMEM_FLOATS (SCR_F + 16384)  // 51392
#define SMEM_BYTES  (SMEM_FLOATS * 4)  // 205568 B

// ---------------------------------------------------------------------------
// f32x2 helpers
// ---------------------------------------------------------------------------
__device__ __forceinline__ unsigned long long pack2(float lo, float hi) {
    unsigned long long r;
    asm("mov.b64 %0, {%1, %2};" : "=l"(r) : "f"(lo), "f"(hi));
    return r;
}
__device__ __forceinline__ void ffma2(unsigned long long& d,
                                      unsigned long long a,
                                      unsigned long long b) {
    asm("fma.rn.f32x2 %0, %1, %2, %0;" : "+l"(d) : "l"(a), "l"(b));
}
__device__ __forceinline__ unsigned long long add2(unsigned long long a,
                                                   unsigned long long b) {
    unsigned long long d;
    asm("add.rn.f32x2 %0, %1, %2;" : "=l"(d) : "l"(a), "l"(b));
    return d;
}
__device__ __forceinline__ float2 unpack2(unsigned long long v) {
    float2 f;
    asm("mov.b64 {%0, %1}, %2;" : "=f"(f.x), "=f"(f.y) : "l"(v));
    return f;
}
__device__ __forceinline__ unsigned ld_acq(const unsigned* p) {
    unsigned v;
    asm volatile("ld.acquire.gpu.u32 %0, [%1];" : "=r"(v) : "l"(p) : "memory");
    return v;
}

__device__ __forceinline__ float sigmoidf_(float x) {
    return 1.0f / (1.0f + __expf(-x));
}
__device__ __forceinline__ float tanh_fast(float x) {
    float a = fabsf(x);
    float e = __expf(-2.0f * a);
    float r = (1.0f - e) / (1.0f + e);
    return copysignf(r, x);
}

// 4x4 transpose across lane quads: lane j of each quad holds M[j][0..3];
// afterwards lane j holds M[0..3][j].
__device__ __forceinline__ void transpose4(float4& v, int lane) {
    const unsigned m = 0xFFFFFFFFu;
    const int j = lane & 3;
    float s0 = (j & 1) ? v.x : v.y;
    float s1 = (j & 1) ? v.z : v.w;
    float r0 = __shfl_xor_sync(m, s0, 1);
    float r1 = __shfl_xor_sync(m, s1, 1);
    if (j & 1) { v.x = r0; v.z = r1; } else { v.y = r0; v.w = r1; }
    s0 = (j & 2) ? v.x : v.z;
    s1 = (j & 2) ? v.y : v.w;
    r0 = __shfl_xor_sync(m, s0, 2);
    r1 = __shfl_xor_sync(m, s1, 2);
    if (j & 2) { v.x = r0; v.y = r1; } else { v.z = r0; v.w = r1; }
}

// ---------------------------------------------------------------------------
// init: zero grid-barrier counter (graph replays restart fresh)
// ---------------------------------------------------------------------------
__global__ void init_bar_kernel() {
    if (threadIdx.x == 0) g_barrier = 0u;
}

// ---------------------------------------------------------------------------
// x_proj = x @ W_ih + bias  (M=16384, N=4096, K=1024) — plain-FFMA SGEMM
// ---------------------------------------------------------------------------
__global__ __launch_bounds__(256) void sgemm_xproj(const float* __restrict__ A,
                                                   const float* __restrict__ Bm,
                                                   const float* __restrict__ bias) {
    __shared__ __align__(16) float As[8 * 128];
    __shared__ __align__(16) float Bs[8 * 128];

    const int tid = threadIdx.x;
    const int rowBase = blockIdx.y * 128;
    const int colBase = blockIdx.x * 128;

    const int irA = tid >> 1;
    const int icA = (tid & 1) * 4;
    const int irB = tid >> 5;
    const int icB = (tid & 31) * 4;

    const int trow = tid >> 4;
    const int tcol = tid & 15;

    float res[8][8];
#pragma unroll
    for (int i = 0; i < 8; i++)
#pragma unroll
        for (int j = 0; j < 8; j++) res[i][j] = 0.0f;

    for (int bk = 0; bk < ND; bk += 8) {
        float4 a = *(const float4*)&A[(size_t)(rowBase + irA) * ND + bk + icA];
        As[(icA + 0) * 128 + irA] = a.x;
        As[(icA + 1) * 128 + irA] = a.y;
        As[(icA + 2) * 128 + irA] = a.z;
        As[(icA + 3) * 128 + irA] = a.w;
        *(float4*)&Bs[irB * 128 + icB] =
            *(const float4*)&Bm[(size_t)(bk + irB) * NG + colBase + icB];
        __syncthreads();

#pragma unroll
        for (int kk = 0; kk < 8; kk++) {
            float regM[8], regN[8];
            *(float4*)&regM[0] = *(float4*)&As[kk * 128 + trow * 8];
            *(float4*)&regM[4] = *(float4*)&As[kk * 128 + trow * 8 + 4];
            *(float4*)&regN[0] = *(float4*)&Bs[kk * 128 + tcol * 8];
            *(float4*)&regN[4] = *(float4*)&Bs[kk * 128 + tcol * 8 + 4];
#pragma unroll
            for (int i = 0; i < 8; i++)
#pragma unroll
                for (int j = 0; j < 8; j++)
                    res[i][j] += regM[i] * regN[j];
        }
        __syncthreads();
    }

#pragma unroll
    for (int i = 0; i < 8; i++) {
#pragma unroll
        for (int j = 0; j < 8; j += 4) {
            int col = colBase + tcol * 8 + j;
            float4 o;
            o.x = res[i][j + 0] + bias[col + 0];
            o.y = res[i][j + 1] + bias[col + 1];
            o.z = res[i][j + 2] + bias[col + 2];
            o.w = res[i][j + 3] + bias[col + 3];
            *(float4*)&g_xproj[(size_t)(rowBase + trow * 8 + i) * NG + col] = o;
        }
    }
}

// ---------------------------------------------------------------------------
// Persistent LSTM recurrence: 128 CTAs x 512 threads, all 512 timesteps.
// CTA owns 8 h-cols (base..base+7) -> 32 gate cols. W slice SMEM-resident.
// Warp w accumulates K-slice {chunk c: k = c*64 + w*4 .. +3}; lanes tile
// 32x32 as (pg: 4 batch-pairs) x (cq: 4 cols) with f32x2 accumulators.
// Cross-CTA h exchange through `out` (ld.global.cg) + software grid barrier.
// ---------------------------------------------------------------------------
__global__ __launch_bounds__(NTHR, 1)
void lstm_persist(const float* __restrict__ Whh, float* __restrict__ out,
                  int write_final) {
    extern __shared__ __align__(16) float sm[];
    float* Ws  = sm + WS_F;
    float* xb  = sm + XB_F;
    float* gbf = sm + GB_F;
    unsigned long long* gb = (unsigned long long*)gbf;
    float* scr = sm + SCR_F;
    unsigned long long* red = (unsigned long long*)scr;

    const int tid  = threadIdx.x;
    const int wid  = tid >> 5;
    const int lane = tid & 31;
    const int base = (int)blockIdx.x * 8;

    // compute-tile roles
    const int pg = lane >> 3;     // batch-pair group: batches 8pg..8pg+7
    const int cq = lane & 7;      // col quad: cols 4cq..4cq+3

    // staging roles (chunk = 64 k x 32 b)
    const int sb   = (wid & 7) * 4 + (lane & 3);           // batch 0..31
    const int sk4  = (lane >> 2) + ((wid >> 3) << 3);      // float4 idx 0..15
    const int sq   = lane & 3;                             // pos in quad
    const int sb0  = (wid & 7) << 2;                       // quad's batch base

    // preload FULL W slice: Ws[k*32 + g*8 + jj] = Whh[k][g*1024 + base + jj]
    // 1024 k-rows x 8 float4-segments = 8192 float4s = 16 iterations x 512 thr
#pragma unroll
    for (int it = 0; it < 16; it++) {
        int idx4 = tid + it * NTHR;        // 0..8191
        int k = idx4 >> 3, seg = idx4 & 7; // seg = g*2 + half
        float4 v = *(const float4*)&Whh[(size_t)k * NG + (seg >> 1) * NH +
                                        base + (seg & 1) * 4];
        *(float4*)&Ws[k * 32 + seg * 4] = v;
    }

    float c_reg = 0.0f;
    unsigned bar_tgt = 0;

    __syncthreads();

    for (int t = 0; t < NT; t++) {
        // x_proj prefetch into xb[b*36 + col]
        if (tid < 256) {
            int b = tid >> 3, g = (tid >> 1) & 3, hf = tid & 1;
            float4 v = *(const float4*)&g_xproj[((size_t)b * NT + t) * NG +
                                                g * NH + base + hf * 4];
            *(float4*)&xb[b * 36 + g * 8 + hf * 4] = v;
        }

        unsigned long long acc[4][4];
#pragma unroll
        for (int i = 0; i < 4; i++)
#pragma unroll
            for (int j = 0; j < 4; j++) acc[i][j] = 0ull;

        if (t > 0) {
            const float* hsrc = out + (size_t)(t - 1) * NH;  // + b*NT*NH

            // stage chunk 0 (transposed [k][b])
            {
                float4 hv = __ldcg((const float4*)(hsrc + (size_t)sb * NT * NH +
                                                   sk4 * 4));
                transpose4(hv, lane);
                *(float4*)&scr[(sk4 * 4 + sq) * 36 + sb0] = hv;
            }
            __syncthreads();

            for (int c = 0; c < 16; c++) {
                float4 nv;
                if (c < 15)
                    nv = __ldcg((const float4*)(hsrc + (size_t)sb * NT * NH +
                                                (c + 1) * 64 + sk4 * 4));

                const float* hb = scr + (c & 1) * 2304;
                const int kbase = wid * 4;
#pragma unroll
                for (int kk = 0; kk < 4; kk++) {
                    const int kl = kbase + kk;
                    ulonglong2 hA = *(const ulonglong2*)&hb[kl * 36 + pg * 8];
                    ulonglong2 hB = *(const ulonglong2*)&hb[kl * 36 + pg * 8 + 4];
                    float4 wv = *(const float4*)&Ws[(c * 64 + kl) * 32 + cq * 4];
                    unsigned long long w0 = pack2(wv.x, wv.x);
                    unsigned long long w1 = pack2(wv.y, wv.y);
                    unsigned long long w2 = pack2(wv.z, wv.z);
                    unsigned long long w3 = pack2(wv.w, wv.w);
                    ffma2(acc[0][0], hA.x, w0); ffma2(acc[0][1], hA.x, w1);
                    ffma2(acc[0][2], hA.x, w2); ffma2(acc[0][3], hA.x, w3);
                    ffma2(acc[1][0], hA.y, w0); ffma2(acc[1][1], hA.y, w1);
                    ffma2(acc[1][2], hA.y, w2); ffma2(acc[1][3], hA.y, w3);
                    ffma2(acc[2][0], hB.x, w0); ffma2(acc[2][1], hB.x, w1);
                    ffma2(acc[2][2], hB.x, w2); ffma2(acc[2][3], hB.x, w3);
                    ffma2(acc[3][0], hB.y, w0); ffma2(acc[3][1], hB.y, w1);
                    ffma2(acc[3][2], hB.y, w2); ffma2(acc[3][3], hB.y, w3);
                }

                if (c < 15) {
                    transpose4(nv, lane);
                    float* hd = scr + ((c + 1) & 1) * 2304;
                    *(float4*)&hd[(sk4 * 4 + sq) * 36 + sb0] = nv;
                }
                __syncthreads();
            }
        } else {
            __syncthreads();   // order xb prefetch before epilogue
        }

        // --- reduction: red[w][col*16 + swizzled pair], swizzle = ^(2*(cq&3))
        {
            unsigned long long* rw = red + wid * 512;
            const int key2 = (cq & 3) << 1;
#pragma unroll
            for (int j = 0; j < 4; j++) {
                int col = cq * 4 + j;
                int p0 = (pg * 4) ^ key2;
                int p1 = (pg * 4 + 2) ^ key2;
                *(ulonglong2*)&rw[col * 16 + p0] =
                    make_ulonglong2(acc[0][j], acc[1][j]);
                *(ulonglong2*)&rw[col * 16 + p1] =
                    make_ulonglong2(acc[2][j], acc[3][j]);
            }
        }
        __syncthreads();

        // sum 16 partials per gate-entry-pair; r=tid -> (col=r>>4, pair=r&15)
        {
            const int col = tid >> 4;
            const int key2 = ((col >> 2) & 3) << 1;
            const int phys = (col << 4) + ((tid & 15) ^ key2);
            unsigned long long s = red[phys];
#pragma unroll
            for (int w = 1; w < 16; w++) s = add2(s, red[w * 512 + phys]);
            gb[col * 17 + (tid & 15)] = s;
        }
        __syncthreads();

        // fused gates + c/h update; thread (b, jj), c in register
        if (tid < 256) {
            const int b = tid >> 3, jj = tid & 7;
            float gate[4];
#pragma unroll
            for (int g = 0; g < 4; g++) {
                int col = g * 8 + jj;
                float r = gbf[(col * 17 + (b >> 1)) * 2 + (b & 1)];
                gate[g] = r + xb[b * 36 + col];
            }
            float ig = sigmoidf_(gate[0]);
            float fg = sigmoidf_(gate[1]);
            float gg = tanh_fast(gate[2]);
            float og = sigmoidf_(gate[3]);
            c_reg = fg * c_reg + ig * gg;
            float h = og * tanh_fast(c_reg);
            out[((size_t)b * NT + t) * NH + base + jj] = h;
            if (write_final && t == NT - 1) {
                out[HSEQ + (size_t)b * NH + base + jj] = h;
                out[HSEQ + (size_t)(NB * NH) + (size_t)b * NH + base + jj] = c_reg;
            }
        }

        // grid barrier (skip after last step)
        if (t < NT - 1) {
            __threadfence();
            __syncthreads();
            bar_tgt += NCTA;
            if (tid == 0) {
                atomicAdd(&g_barrier, 1u);
                while (ld_acq(&g_barrier) < bar_tgt) { }
            }
            __syncthreads();
        }
    }
}

// ---------------------------------------------------------------------------
// launch
// ---------------------------------------------------------------------------
extern "C" void kernel_launch(void* const* d_in, const int* in_sizes, int n_in,
                              void* d_out, int out_size) {
    const float* x    = (const float*)d_in[0];
    const float* wih  = (const float*)d_in[1];
    const float* whh  = (const float*)d_in[2];
    const float* bias = (const float*)d_in[3];
    float* out = (float*)d_out;

    (void)in_sizes; (void)n_in;

    cudaFuncSetAttribute(lstm_persist,
                         cudaFuncAttributeMaxDynamicSharedMemorySize,
                         SMEM_BYTES);

    init_bar_kernel<<<1, 32>>>();

    {
        dim3 grid(NG / 128, MTOT / 128);   // (32, 128)
        sgemm_xproj<<<grid, 256>>>(x, wih, bias);
    }

    int wf = (out_size >= (int)(HSEQ + 2 * NB * NH)) ? 1 : 0;
    lstm_persist<<<NCTA, NTHR, SMEM_BYTES>>>(whh, out, wf);
}

// round 7
// speedup vs baseline: 1.8443x; 1.1984x over previous
#include <cuda_runtime.h>
#include <cuda_bf16.h>
#include <stdint.h>
#include <math.h>

// Problem dims
#define NB   32
#define NT   512
#define ND   1024
#define NH   1024
#define NG   4096
#define MTOT (NB * NT)
#define NCTA 128
#define NTHR 512
#define HSEQ ((size_t)NB * NT * NH)

// Scratch (allocation-free rule: __device__ globals)
__device__ float g_xproj[(size_t)MTOT * NG];            // 256 MB
__device__ unsigned g_barrier;
__device__ __nv_bfloat16 g_ah[(size_t)MTOT * ND];       // x hi
__device__ __nv_bfloat16 g_al[(size_t)MTOT * ND];       // x lo
__device__ __nv_bfloat16 g_bh[(size_t)ND * NG];         // wih hi
__device__ __nv_bfloat16 g_bl[(size_t)ND * NG];         // wih lo

// persistent-kernel smem offsets (floats)
#define WS_F  0
#define XB_F  32768
#define GB_F  (32768 + 1152)
#define SCR_F (GB_F + 1088)
#define SMEM_FLOATS (SCR_F + 16384)
#define SMEM_BYTES  (SMEM_FLOATS * 4)

// mma GEMM tile config
#define A_STRIDE 40
#define B_STRIDE 136
#define A_BUF_B (128 * A_STRIDE * 2)
#define B_BUF_B (32 * B_STRIDE * 2)
#define BUF_B   (2 * A_BUF_B + 2 * B_BUF_B)
#define GEMM_SMEM (2 * BUF_B)

// ---------------------------------------------------------------------------
// helpers
// ---------------------------------------------------------------------------
__device__ __forceinline__ unsigned long long pack2(float lo, float hi) {
    unsigned long long r;
    asm("mov.b64 %0, {%1, %2};" : "=l"(r) : "f"(lo), "f"(hi));
    return r;
}

__device__ __forceinline__ void ffma2(unsigned long long& d,
                                      unsigned long long a,
                                      unsigned long long b) {
    asm("fma.rn.f32x2 %0, %1, %2, %0;" : "+l"(d) : "l"(a), "l"(b));
}

__device__ __forceinline__ unsigned long long add2(unsigned long long a,
                                                   unsigned long long b) {
    unsigned long long d;
    asm("add.rn.f32x2 %0, %1, %2;" : "=l"(d) : "l"(a), "l"(b));
    return d;
}

__device__ __forceinline__ unsigned ld_acq(const unsigned* p) {
    unsigned v;
    asm volatile("ld.acquire.gpu.u32 %0, [%1];" : "=r"(v) : "l"(p) : "memory");
    return v;
}

__device__ __forceinline__ float sigmoidf_(float x) {
    return 1.0f / (1.0f + __expf(-x));
}

__device__ __forceinline__ float tanh_fast(float x) {
    float a = fabsf(x);
    float e = __expf(-2.0f * a);
    float r = (1.0f - e) / (1.0f + e);
    return copysignf(r, x);
}

__device__ __forceinline__ uint32_t smem_u32(const void* p) {
    uint32_t a;
    asm("{ .reg .u64 t; cvta.to.shared.u64 t, %1; cvt.u32.u64 %0, t; }"
        : "=r"(a) : "l"(p));
    return a;
}

__device__ __forceinline__ void cpa16(uint32_t dst, const void* src) {
    asm volatile("cp.async.ca.shared.global [%0], [%1], 16;"
                 :: "r"(dst), "l"(src));
}

__device__ __forceinline__ void cp_commit() {
    asm volatile("cp.async.commit_group;");
}

template <int N>
__device__ __forceinline__ void cp_wait() {
    asm volatile("cp.async.wait_group %0;" :: "n"(N));
}

__device__ __forceinline__ void ldm_x4(uint32_t* r, uint32_t addr) {
    asm volatile("ldmatrix.sync.aligned.m8n8.x4.shared.b16 {%0,%1,%2,%3}, [%4];"
                 : "=r"(r[0]), "=r"(r[1]), "=r"(r[2]), "=r"(r[3]) : "r"(addr));
}

__device__ __forceinline__ void ldm_x4_t(uint32_t* r, uint32_t addr) {
    asm volatile("ldmatrix.sync.aligned.m8n8.x4.trans.shared.b16 {%0,%1,%2,%3}, [%4];"
                 : "=r"(r[0]), "=r"(r[1]), "=r"(r[2]), "=r"(r[3]) : "r"(addr));
}

__device__ __forceinline__ void mma16816(float* d, const uint32_t* a,
                                         const uint32_t* b) {
    asm volatile(
        "mma.sync.aligned.m16n8k16.row.col.f32.bf16.bf16.f32 "
        "{%0,%1,%2,%3}, {%4,%5,%6,%7}, {%8,%9}, {%0,%1,%2,%3};"
        : "+f"(d[0]), "+f"(d[1]), "+f"(d[2]), "+f"(d[3])
        : "r"(a[0]), "r"(a[1]), "r"(a[2]), "r"(a[3]), "r"(b[0]), "r"(b[1]));
}

__device__ __forceinline__ void transpose4(float4& v, int lane) {
    const unsigned m = 0xFFFFFFFFu;
    const int j = lane & 3;
    float s0 = (j & 1) ? v.x : v.y;
    float s1 = (j & 1) ? v.z : v.w;
    float r0 = __shfl_xor_sync(m, s0, 1);
    float r1 = __shfl_xor_sync(m, s1, 1);
    if (j & 1) { v.x = r0; v.z = r1; } else { v.y = r0; v.w = r1; }
    s0 = (j & 2) ? v.x : v.z;
    s1 = (j & 2) ? v.y : v.w;
    r0 = __shfl_xor_sync(m, s0, 2);
    r1 = __shfl_xor_sync(m, s1, 2);
    if (j & 2) { v.x = r0; v.y = r1; } else { v.z = r0; v.w = r1; }
}

// ---------------------------------------------------------------------------
__global__ void init_bar_kernel() {
    if (threadIdx.x == 0) g_barrier = 0u;
}

// ---------------------------------------------------------------------------
// split x and wih into bf16 hi + bf16 residual
// ---------------------------------------------------------------------------
__global__ __launch_bounds__(256) void split_kernel(const float* __restrict__ x,
                                                    const float* __restrict__ wih) {
    size_t i = (size_t)blockIdx.x * blockDim.x + threadIdx.x;
    if (i < (size_t)MTOT * ND) {
        float a = x[i];
        __nv_bfloat16 h = __float2bfloat16(a);
        g_ah[i] = h;
        g_al[i] = __float2bfloat16(a - __bfloat162float(h));
    }
    if (i < (size_t)ND * NG) {
        float b = wih[i];
        __nv_bfloat16 h = __float2bfloat16(b);
        g_bh[i] = h;
        g_bl[i] = __float2bfloat16(b - __bfloat162float(h));
    }
}

// ---------------------------------------------------------------------------
// x_proj = x @ W_ih + bias via split-bf16 mma.sync (m16n8k16)
// ---------------------------------------------------------------------------
__device__ __forceinline__ void stage_chunk(uint32_t sbuf, int kc, int rowBase,
                                            int colBase, int tid) {
    for (int i = 0; i < 2; i++) {
        int idx = tid + i * 256;
        int row = idx >> 2;
        int c4 = idx & 3;
        size_t goff = (size_t)(rowBase + row) * ND + kc * 32 + c4 * 8;
        uint32_t d = sbuf + row * (A_STRIDE * 2) + c4 * 16;
        cpa16(d, g_ah + goff);
        cpa16(d + A_BUF_B, g_al + goff);
    }
    for (int i = 0; i < 2; i++) {
        int idx = tid + i * 256;
        int row = idx >> 4;
        int c16 = idx & 15;
        size_t goff = (size_t)(kc * 32 + row) * NG + colBase + c16 * 8;
        uint32_t d = sbuf + 2 * A_BUF_B + row * (B_STRIDE * 2) + c16 * 16;
        cpa16(d, g_bh + goff);
        cpa16(d + B_BUF_B, g_bl + goff);
    }
}

__global__ __launch_bounds__(256) void mma_xproj(const float* __restrict__ bias) {
    extern __shared__ __align__(16) char gsm[];
    const uint32_t sb0 = smem_u32(gsm);

    const int tid = threadIdx.x;
    const int lane = tid & 31;
    const int wid = tid >> 5;
    const int warp_m = wid >> 2;
    const int warp_n = wid & 3;
    const int rowBase = blockIdx.y * 128;
    const int colBase = blockIdx.x * 128;

    float acc[4][4][4];
    for (int mt = 0; mt < 4; mt++)
        for (int nt = 0; nt < 4; nt++)
            for (int r = 0; r < 4; r++)
                acc[mt][nt][r] = 0.0f;

    stage_chunk(sb0, 0, rowBase, colBase, tid);
    cp_commit();

    for (int c = 0; c < 32; c++) {
        if (c < 31) {
            stage_chunk(sb0 + ((c + 1) & 1) * BUF_B, c + 1, rowBase, colBase, tid);
            cp_commit();
            cp_wait<1>();
        } else {
            cp_wait<0>();
        }
        __syncthreads();

        const uint32_t sb = sb0 + (c & 1) * BUF_B;
        for (int ks = 0; ks < 2; ks++) {
            uint32_t ah[4][4], al[4][4], bh[2][4], bl[2][4];
            for (int mt = 0; mt < 4; mt++) {
                uint32_t ad = sb +
                    (warp_m * 64 + mt * 16 + (lane & 15)) * (A_STRIDE * 2) +
                    ks * 32 + (lane >> 4) * 16;
                ldm_x4(ah[mt], ad);
                ldm_x4(al[mt], ad + A_BUF_B);
            }
            for (int np = 0; np < 2; np++) {
                uint32_t bd = sb + 2 * A_BUF_B +
                    (ks * 16 + (lane & 15)) * (B_STRIDE * 2) +
                    (warp_n * 32 + np * 16 + (lane >> 4) * 8) * 2;
                ldm_x4_t(bh[np], bd);
                ldm_x4_t(bl[np], bd + B_BUF_B);
            }
            for (int mt = 0; mt < 4; mt++) {
                for (int np = 0; np < 2; np++) {
                    mma16816(acc[mt][2 * np],     ah[mt], &bh[np][0]);
                    mma16816(acc[mt][2 * np + 1], ah[mt], &bh[np][2]);
                    mma16816(acc[mt][2 * np],     ah[mt], &bl[np][0]);
                    mma16816(acc[mt][2 * np + 1], ah[mt], &bl[np][2]);
                    mma16816(acc[mt][2 * np],     al[mt], &bh[np][0]);
                    mma16816(acc[mt][2 * np + 1], al[mt], &bh[np][2]);
                }
            }
        }
        __syncthreads();
    }

    for (int mt = 0; mt < 4; mt++) {
        for (int nt = 0; nt < 4; nt++) {
            int row = rowBase + warp_m * 64 + mt * 16 + (lane >> 2);
            int col = colBase + warp_n * 32 + nt * 8 + (lane & 3) * 2;
            float b0 = bias[col];
            float b1 = bias[col + 1];
            float2 v0 = make_float2(acc[mt][nt][0] + b0, acc[mt][nt][1] + b1);
            float2 v1 = make_float2(acc[mt][nt][2] + b0, acc[mt][nt][3] + b1);
            *(float2*)&g_xproj[(size_t)row * NG + col] = v0;
            *(float2*)&g_xproj[(size_t)(row + 8) * NG + col] = v1;
        }
    }
}

// ---------------------------------------------------------------------------
// recurrence inner-chunk compute (64 k values), extracted for clarity
// ---------------------------------------------------------------------------
__device__ __forceinline__ void step_compute(const float* hb, const float* wsc,
                                             int kbase, int pg, int cq,
                                             unsigned long long acc[4][4]) {
#pragma unroll
    for (int kk = 0; kk < 4; kk++) {
        const int kl = kbase + kk;
        ulonglong2 hA = *(const ulonglong2*)(hb + kl * 36 + pg * 8);
        ulonglong2 hB = *(const ulonglong2*)(hb + kl * 36 + pg * 8 + 4);
        float4 wv = *(const float4*)(wsc + kl * 32 + cq * 4);
        unsigned long long w0 = pack2(wv.x, wv.x);
        unsigned long long w1 = pack2(wv.y, wv.y);
        unsigned long long w2 = pack2(wv.z, wv.z);
        unsigned long long w3 = pack2(wv.w, wv.w);
        ffma2(acc[0][0], hA.x, w0);
        ffma2(acc[0][1], hA.x, w1);
        ffma2(acc[0][2], hA.x, w2);
        ffma2(acc[0][3], hA.x, w3);
        ffma2(acc[1][0], hA.y, w0);
        ffma2(acc[1][1], hA.y, w1);
        ffma2(acc[1][2], hA.y, w2);
        ffma2(acc[1][3], hA.y, w3);
        ffma2(acc[2][0], hB.x, w0);
        ffma2(acc[2][1], hB.x, w1);
        ffma2(acc[2][2], hB.x, w2);
        ffma2(acc[2][3], hB.x, w3);
        ffma2(acc[3][0], hB.y, w0);
        ffma2(acc[3][1], hB.y, w1);
        ffma2(acc[3][2], hB.y, w2);
        ffma2(acc[3][3], hB.y, w3);
    }
}

__device__ __forceinline__ void write_partials(unsigned long long* red, int wid,
                                               int pg, int cq,
                                               const unsigned long long acc[4][4]) {
    unsigned long long* rw = red + wid * 512;
    const int key2 = (cq & 3) << 1;
#pragma unroll
    for (int j = 0; j < 4; j++) {
        int col = cq * 4 + j;
        int p0 = (pg * 4) ^ key2;
        int p1 = (pg * 4 + 2) ^ key2;
        *(ulonglong2*)(rw + col * 16 + p0) = make_ulonglong2(acc[0][j], acc[1][j]);
        *(ulonglong2*)(rw + col * 16 + p1) = make_ulonglong2(acc[2][j], acc[3][j]);
    }
}

// ---------------------------------------------------------------------------
// Persistent LSTM recurrence (logic identical to R5)
// ---------------------------------------------------------------------------
__global__ __launch_bounds__(NTHR, 1)
void lstm_persist(const float* __restrict__ Whh, float* __restrict__ out,
                  int write_final) {
    extern __shared__ __align__(16) float sm[];
    float* Ws = sm + WS_F;
    float* xb = sm + XB_F;
    float* gbf = sm + GB_F;
    unsigned long long* gb = (unsigned long long*)gbf;
    float* scr = sm + SCR_F;
    unsigned long long* red = (unsigned long long*)scr;

    const int tid = threadIdx.x;
    const int wid = tid >> 5;
    const int lane = tid & 31;
    const int base = (int)blockIdx.x * 8;

    const int pg = lane >> 3;
    const int cq = lane & 7;

    const int sb = (wid & 7) * 4 + (lane & 3);
    const int sk4 = (lane >> 2) + ((wid >> 3) << 3);
    const int sq = lane & 3;
    const int sb0 = (wid & 7) << 2;

#pragma unroll
    for (int it = 0; it < 16; it++) {
        int idx4 = tid + it * NTHR;
        int k = idx4 >> 3;
        int seg = idx4 & 7;
        float4 v = *(const float4*)&Whh[(size_t)k * NG + (seg >> 1) * NH +
                                        base + (seg & 1) * 4];
        *(float4*)&Ws[k * 32 + seg * 4] = v;
    }

    float c_reg = 0.0f;
    unsigned bar_tgt = 0;

    __syncthreads();

    for (int t = 0; t < NT; t++) {
        if (tid < 256) {
            int b = tid >> 3;
            int g = (tid >> 1) & 3;
            int hf = tid & 1;
            float4 v = *(const float4*)&g_xproj[((size_t)b * NT + t) * NG +
                                                g * NH + base + hf * 4];
            *(float4*)&xb[b * 36 + g * 8 + hf * 4] = v;
        }

        unsigned long long acc[4][4];
        for (int i = 0; i < 4; i++)
            for (int j = 0; j < 4; j++)
                acc[i][j] = 0ull;

        if (t > 0) {
            const float* hsrc = out + (size_t)(t - 1) * NH;

            float4 hv = __ldcg((const float4*)(hsrc + (size_t)sb * NT * NH +
                                               sk4 * 4));
            transpose4(hv, lane);
            *(float4*)&scr[(sk4 * 4 + sq) * 36 + sb0] = hv;
            __syncthreads();

            for (int c = 0; c < 16; c++) {
                float4 nv = make_float4(0.f, 0.f, 0.f, 0.f);
                if (c < 15) {
                    nv = __ldcg((const float4*)(hsrc + (size_t)sb * NT * NH +
                                                (c + 1) * 64 + sk4 * 4));
                }

                const float* hb = scr + (c & 1) * 2304;
                step_compute(hb, Ws + c * 64 * 32, wid * 4, pg, cq, acc);

                if (c < 15) {
                    transpose4(nv, lane);
                    float* hd = scr + ((c + 1) & 1) * 2304;
                    *(float4*)&hd[(sk4 * 4 + sq) * 36 + sb0] = nv;
                }
                __syncthreads();
            }
        } else {
            __syncthreads();
        }

        write_partials(red, wid, pg, cq, acc);
        __syncthreads();

        {
            const int col = tid >> 4;
            const int key2 = ((col >> 2) & 3) << 1;
            const int phys = (col << 4) + ((tid & 15) ^ key2);
            unsigned long long s = red[phys];
#pragma unroll
            for (int w = 1; w < 16; w++) {
                s = add2(s, red[w * 512 + phys]);
            }
            gb[col * 17 + (tid & 15)] = s;
        }
        __syncthreads();

        if (tid < 256) {
            const int b = tid >> 3;
            const int jj = tid & 7;
            float gate[4];
#pragma unroll
            for (int g = 0; g < 4; g++) {
                int col = g * 8 + jj;
                float r = gbf[(col * 17 + (b >> 1)) * 2 + (b & 1)];
                gate[g] = r + xb[b * 36 + col];
            }
            float ig = sigmoidf_(gate[0]);
            float fg = sigmoidf_(gate[1]);
            float gg = tanh_fast(gate[2]);
            float og = sigmoidf_(gate[3]);
            c_reg = fg * c_reg + ig * gg;
            float h = og * tanh_fast(c_reg);
            out[((size_t)b * NT + t) * NH + base + jj] = h;
            if (write_final && t == NT - 1) {
                out[HSEQ + (size_t)b * NH + base + jj] = h;
                out[HSEQ + (size_t)(NB * NH) + (size_t)b * NH + base + jj] = c_reg;
            }
        }

        if (t < NT - 1) {
            __threadfence();
            __syncthreads();
            bar_tgt += NCTA;
            if (tid == 0) {
                atomicAdd(&g_barrier, 1u);
                while (ld_acq(&g_barrier) < bar_tgt) { }
            }
            __syncthreads();
        }
    }
}

// ---------------------------------------------------------------------------
// launch
// ---------------------------------------------------------------------------
extern "C" void kernel_launch(void* const* d_in, const int* in_sizes, int n_in,
                              void* d_out, int out_size) {
    const float* x = (const float*)d_in[0];
    const float* wih = (const float*)d_in[1];
    const float* whh = (const float*)d_in[2];
    const float* bias = (const float*)d_in[3];
    float* out = (float*)d_out;

    (void)in_sizes;
    (void)n_in;

    cudaFuncSetAttribute(lstm_persist,
                         cudaFuncAttributeMaxDynamicSharedMemorySize,
                         SMEM_BYTES);
    cudaFuncSetAttribute(mma_xproj,
                         cudaFuncAttributeMaxDynamicSharedMemorySize,
                         GEMM_SMEM);

    init_bar_kernel<<<1, 32>>>();

    split_kernel<<<(MTOT * ND) / 256, 256>>>(x, wih);

    dim3 grid(NG / 128, MTOT / 128);
    mma_xproj<<<grid, 256, GEMM_SMEM>>>(bias);

    int wf = (out_size >= (int)(HSEQ + 2 * NB * NH)) ? 1 : 0;
    lstm_persist<<<NCTA, NTHR, SMEM_BYTES>>>(whh, out, wf);
}

// round 9
// speedup vs baseline: 3.1975x; 1.7337x over previous
#include <cuda_runtime.h>
#include <cuda_bf16.h>
#include <stdint.h>
#include <math.h>

// Problem dims
#define NB   32
#define NT   512
#define ND   1024
#define NH   1024
#define NG   4096
#define MTOT (NB * NT)
#define NCTA 128
#define NTHR 512
#define HSEQ ((size_t)NB * NT * NH)

// Scratch (allocation-free rule: __device__ globals)
__device__ float g_xproj[(size_t)MTOT * NG];            // 256 MB
__device__ unsigned g_barrier;
__device__ __nv_bfloat16 g_ah[(size_t)MTOT * ND];       // x hi
__device__ __nv_bfloat16 g_al[(size_t)MTOT * ND];       // x lo
__device__ __nv_bfloat16 g_bh[(size_t)ND * NG];         // wih hi
__device__ __nv_bfloat16 g_bl[(size_t)ND * NG];         // wih lo
__device__ __nv_bfloat16 g_hh[NB * NH];                 // h hi (per step)
__device__ __nv_bfloat16 g_hl[NB * NH];                 // h lo (per step)

// mma GEMM tile config (xproj)
#define A_STRIDE 40
#define B_STRIDE 136
#define A_BUF_B (128 * A_STRIDE * 2)
#define B_BUF_B (32 * B_STRIDE * 2)
#define BUF_B   (2 * A_BUF_B + 2 * B_BUF_B)
#define GEMM_SMEM (2 * BUF_B)

// persistent-kernel smem byte offsets
//   wh/wl [1024][40] bf16 (stride 80 B = 5x16: ldmatrix-aligned, conflict-free)
//   scr   = max(2 h-buffers 2x17408, red 16x2304) = 36864
//   h buffer: hh[32][136] bf16 (stride 272 B = 17x16) then hl same
#define WH_B   0
#define WL_B   81920
#define SCR_B  163840
#define HBUF_STRIDE_B 17408
#define HROW_B 272
#define HLO_OFF 8704
#define XB_B   200704
#define GB_B   205312
#define PERSIST_SMEM 209664

// ---------------------------------------------------------------------------
// helpers
// ---------------------------------------------------------------------------
__device__ __forceinline__ unsigned ld_acq(const unsigned* p) {
    unsigned v;
    asm volatile("ld.acquire.gpu.u32 %0, [%1];" : "=r"(v) : "l"(p) : "memory");
    return v;
}

__device__ __forceinline__ float sigmoidf_(float x) {
    return 1.0f / (1.0f + __expf(-x));
}

__device__ __forceinline__ float tanh_fast(float x) {
    float a = fabsf(x);
    float e = __expf(-2.0f * a);
    float r = (1.0f - e) / (1.0f + e);
    return copysignf(r, x);
}

__device__ __forceinline__ uint32_t smem_u32(const void* p) {
    uint32_t a;
    asm("{ .reg .u64 t; cvta.to.shared.u64 t, %1; cvt.u32.u64 %0, t; }"
        : "=r"(a) : "l"(p));
    return a;
}

__device__ __forceinline__ void cpa16(uint32_t dst, const void* src) {
    asm volatile("cp.async.ca.shared.global [%0], [%1], 16;"
                 :: "r"(dst), "l"(src));
}

__device__ __forceinline__ void cpa16_cg(uint32_t dst, const void* src) {
    asm volatile("cp.async.cg.shared.global [%0], [%1], 16;"
                 :: "r"(dst), "l"(src));
}

__device__ __forceinline__ void cp_commit() {
    asm volatile("cp.async.commit_group;");
}

template <int N>
__device__ __forceinline__ void cp_wait() {
    asm volatile("cp.async.wait_group %0;" :: "n"(N));
}

__device__ __forceinline__ void ldm_x4(uint32_t* r, uint32_t addr) {
    asm volatile("ldmatrix.sync.aligned.m8n8.x4.shared.b16 {%0,%1,%2,%3}, [%4];"
                 : "=r"(r[0]), "=r"(r[1]), "=r"(r[2]), "=r"(r[3]) : "r"(addr));
}

__device__ __forceinline__ void ldm_x4_t(uint32_t* r, uint32_t addr) {
    asm volatile("ldmatrix.sync.aligned.m8n8.x4.trans.shared.b16 {%0,%1,%2,%3}, [%4];"
                 : "=r"(r[0]), "=r"(r[1]), "=r"(r[2]), "=r"(r[3]) : "r"(addr));
}

__device__ __forceinline__ void mma16816(float* d, const uint32_t* a,
                                         const uint32_t* b) {
    asm volatile(
        "mma.sync.aligned.m16n8k16.row.col.f32.bf16.bf16.f32 "
        "{%0,%1,%2,%3}, {%4,%5,%6,%7}, {%8,%9}, {%0,%1,%2,%3};"
        : "+f"(d[0]), "+f"(d[1]), "+f"(d[2]), "+f"(d[3])
        : "r"(a[0]), "r"(a[1]), "r"(a[2]), "r"(a[3]), "r"(b[0]), "r"(b[1]));
}

// ---------------------------------------------------------------------------
__global__ void init_bar_kernel() {
    if (threadIdx.x == 0) g_barrier = 0u;
}

// ---------------------------------------------------------------------------
// split x and wih into bf16 hi + bf16 residual
// ---------------------------------------------------------------------------
__global__ __launch_bounds__(256) void split_kernel(const float* __restrict__ x,
                                                    const float* __restrict__ wih) {
    size_t i = (size_t)blockIdx.x * blockDim.x + threadIdx.x;
    if (i < (size_t)MTOT * ND) {
        float a = x[i];
        __nv_bfloat16 h = __float2bfloat16(a);
        g_ah[i] = h;
        g_al[i] = __float2bfloat16(a - __bfloat162float(h));
    }
    if (i < (size_t)ND * NG) {
        float b = wih[i];
        __nv_bfloat16 h = __float2bfloat16(b);
        g_bh[i] = h;
        g_bl[i] = __float2bfloat16(b - __bfloat162float(h));
    }
}

// ---------------------------------------------------------------------------
// x_proj = x @ W_ih + bias via split-bf16 mma.sync (unchanged from R7, passing)
// ---------------------------------------------------------------------------
__device__ __forceinline__ void stage_chunk(uint32_t sbuf, int kc, int rowBase,
                                            int colBase, int tid) {
    for (int i = 0; i < 2; i++) {
        int idx = tid + i * 256;
        int row = idx >> 2;
        int c4 = idx & 3;
        size_t goff = (size_t)(rowBase + row) * ND + kc * 32 + c4 * 8;
        uint32_t d = sbuf + row * (A_STRIDE * 2) + c4 * 16;
        cpa16(d, g_ah + goff);
        cpa16(d + A_BUF_B, g_al + goff);
    }
    for (int i = 0; i < 2; i++) {
        int idx = tid + i * 256;
        int row = idx >> 4;
        int c16 = idx & 15;
        size_t goff = (size_t)(kc * 32 + row) * NG + colBase + c16 * 8;
        uint32_t d = sbuf + 2 * A_BUF_B + row * (B_STRIDE * 2) + c16 * 16;
        cpa16(d, g_bh + goff);
        cpa16(d + B_BUF_B, g_bl + goff);
    }
}

__global__ __launch_bounds__(256) void mma_xproj(const float* __restrict__ bias) {
    extern __shared__ __align__(16) char gsm[];
    const uint32_t sb0 = smem_u32(gsm);

    const int tid = threadIdx.x;
    const int lane = tid & 31;
    const int wid = tid >> 5;
    const int warp_m = wid >> 2;
    const int warp_n = wid & 3;
    const int rowBase = blockIdx.y * 128;
    const int colBase = blockIdx.x * 128;

    float acc[4][4][4];
    for (int mt = 0; mt < 4; mt++)
        for (int nt = 0; nt < 4; nt++)
            for (int r = 0; r < 4; r++)
                acc[mt][nt][r] = 0.0f;

    stage_chunk(sb0, 0, rowBase, colBase, tid);
    cp_commit();

    for (int c = 0; c < 32; c++) {
        if (c < 31) {
            stage_chunk(sb0 + ((c + 1) & 1) * BUF_B, c + 1, rowBase, colBase, tid);
            cp_commit();
            cp_wait<1>();
        } else {
            cp_wait<0>();
        }
        __syncthreads();

        const uint32_t sb = sb0 + (c & 1) * BUF_B;
        for (int ks = 0; ks < 2; ks++) {
            uint32_t ah[4][4], al[4][4], bh[2][4], bl[2][4];
            for (int mt = 0; mt < 4; mt++) {
                uint32_t ad = sb +
                    (warp_m * 64 + mt * 16 + (lane & 15)) * (A_STRIDE * 2) +
                    ks * 32 + (lane >> 4) * 16;
                ldm_x4(ah[mt], ad);
                ldm_x4(al[mt], ad + A_BUF_B);
            }
            for (int np = 0; np < 2; np++) {
                uint32_t bd = sb + 2 * A_BUF_B +
                    (ks * 16 + (lane & 15)) * (B_STRIDE * 2) +
                    (warp_n * 32 + np * 16 + (lane >> 4) * 8) * 2;
                ldm_x4_t(bh[np], bd);
                ldm_x4_t(bl[np], bd + B_BUF_B);
            }
            for (int mt = 0; mt < 4; mt++) {
                for (int np = 0; np < 2; np++) {
                    mma16816(acc[mt][2 * np],     ah[mt], &bh[np][0]);
                    mma16816(acc[mt][2 * np + 1], ah[mt], &bh[np][2]);
                    mma16816(acc[mt][2 * np],     ah[mt], &bl[np][0]);
                    mma16816(acc[mt][2 * np + 1], ah[mt], &bl[np][2]);
                    mma16816(acc[mt][2 * np],     al[mt], &bh[np][0]);
                    mma16816(acc[mt][2 * np + 1], al[mt], &bh[np][2]);
                }
            }
        }
        __syncthreads();
    }

    for (int mt = 0; mt < 4; mt++) {
        for (int nt = 0; nt < 4; nt++) {
            int row = rowBase + warp_m * 64 + mt * 16 + (lane >> 2);
            int col = colBase + warp_n * 32 + nt * 8 + (lane & 3) * 2;
            float b0 = bias[col];
            float b1 = bias[col + 1];
            float2 v0 = make_float2(acc[mt][nt][0] + b0, acc[mt][nt][1] + b1);
            float2 v1 = make_float2(acc[mt][nt][2] + b0, acc[mt][nt][3] + b1);
            *(float2*)&g_xproj[(size_t)row * NG + col] = v0;
            *(float2*)&g_xproj[(size_t)(row + 8) * NG + col] = v1;
        }
    }
}

// ---------------------------------------------------------------------------
// recurrence: stage one 128-k chunk of split h (cg = skip L1; fresh across bar)
// buffer: hh[32][136] bf16, then hl[32][136] bf16
// ---------------------------------------------------------------------------
__device__ __forceinline__ void stage_h_chunk(uint32_t hbuf, int c, int tid) {
    int row = tid >> 4;          // 0..31
    int seg = tid & 15;          // 16 segs x 8 bf16 = 128 k
    const __nv_bfloat16* srch = g_hh + row * NH + c * 128 + seg * 8;
    const __nv_bfloat16* srcl = g_hl + row * NH + c * 128 + seg * 8;
    uint32_t d = hbuf + row * HROW_B + seg * 16;
    cpa16_cg(d, srch);
    cpa16_cg(d + HLO_OFF, srcl);
}

// per-warp compute for one chunk: warp = (ks = wid&7: k16 slice, ch = wid>>3:
// col half). acc[mt 0..1][nt 0..1][4] covers 32 batches x 16 cols.
__device__ __forceinline__ void rec_compute(uint32_t hbuf, uint32_t wh,
                                            uint32_t wl, int c, int ks, int ch,
                                            int lane, float acc[2][2][4]) {
    uint32_t ahh[2][4], ahl[2][4], bh[4], bl[4];
    for (int mt = 0; mt < 2; mt++) {
        uint32_t ad = hbuf + (mt * 16 + (lane & 15)) * HROW_B +
                      ks * 32 + (lane >> 4) * 16;
        ldm_x4(ahh[mt], ad);
        ldm_x4(ahl[mt], ad + HLO_OFF);
    }
    {
        uint32_t krow = c * 128 + ks * 16 + (lane & 15);
        uint32_t coff = ch * 32 + (lane >> 4) * 16;   // bytes within 40-col row
        ldm_x4_t(bh, wh + krow * 80 + coff);
        ldm_x4_t(bl, wl + krow * 80 + coff);
    }
    for (int mt = 0; mt < 2; mt++) {
        mma16816(acc[mt][0], ahh[mt], &bh[0]);
        mma16816(acc[mt][1], ahh[mt], &bh[2]);
        mma16816(acc[mt][0], ahh[mt], &bl[0]);
        mma16816(acc[mt][1], ahh[mt], &bl[2]);
        mma16816(acc[mt][0], ahl[mt], &bh[0]);
        mma16816(acc[mt][1], ahl[mt], &bh[2]);
    }
}

// write warp partials: red[w][row 32][col 16 (+2 pad)]
__device__ __forceinline__ void write_partials(float* red, int wid, int lane,
                                               const float acc[2][2][4]) {
    float* rw = red + wid * 576;
    for (int mt = 0; mt < 2; mt++) {
        for (int nt = 0; nt < 2; nt++) {
            int row = mt * 16 + (lane >> 2);
            int col = nt * 8 + (lane & 3) * 2;
            *(float2*)&rw[row * 18 + col] =
                make_float2(acc[mt][nt][0], acc[mt][nt][1]);
            *(float2*)&rw[(row + 8) * 18 + col] =
                make_float2(acc[mt][nt][2], acc[mt][nt][3]);
        }
    }
}

// ---------------------------------------------------------------------------
// Persistent LSTM recurrence with split-bf16 tensor cores
// ---------------------------------------------------------------------------
__global__ __launch_bounds__(NTHR, 1)
void lstm_persist(const float* __restrict__ Whh, float* __restrict__ out,
                  int write_final) {
    extern __shared__ __align__(16) char smx[];
    __nv_bfloat16* wh = (__nv_bfloat16*)(smx + WH_B);
    __nv_bfloat16* wl = (__nv_bfloat16*)(smx + WL_B);
    float* red = (float*)(smx + SCR_B);
    float* xb  = (float*)(smx + XB_B);
    float* gb  = (float*)(smx + GB_B);
    const uint32_t sm0 = smem_u32(smx);
    const uint32_t wh_a = sm0 + WH_B;
    const uint32_t wl_a = sm0 + WL_B;
    const uint32_t scr_a = sm0 + SCR_B;

    const int tid = threadIdx.x;
    const int wid = tid >> 5;
    const int lane = tid & 31;
    const int base = (int)blockIdx.x * 8;
    const int ks = wid & 7;
    const int ch = wid >> 3;

    // preload + split W slice: wh/wl[k][40] (cols 0..31 used)
    for (int it = 0; it < 64; it++) {
        int idx = tid + it * NTHR;        // 0..32767
        int k = idx >> 5;
        int col = idx & 31;
        float w = Whh[(size_t)k * NG + (col >> 3) * NH + base + (col & 7)];
        __nv_bfloat16 hi = __float2bfloat16(w);
        wh[k * 40 + col] = hi;
        wl[k * 40 + col] = __float2bfloat16(w - __bfloat162float(hi));
    }

    float c_reg = 0.0f;
    unsigned bar_tgt = 0;

    __syncthreads();

    for (int t = 0; t < NT; t++) {
        // x_proj prefetch into xb[b*36 + col]
        if (tid < 256) {
            int b = tid >> 3;
            int g = (tid >> 1) & 3;
            int hf = tid & 1;
            float4 v = *(const float4*)&g_xproj[((size_t)b * NT + t) * NG +
                                                g * NH + base + hf * 4];
            *(float4*)&xb[b * 36 + g * 8 + hf * 4] = v;
        }

        float acc[2][2][4];
        for (int mt = 0; mt < 2; mt++)
            for (int nt = 0; nt < 2; nt++)
                for (int r = 0; r < 4; r++)
                    acc[mt][nt][r] = 0.0f;

        if (t > 0) {
            stage_h_chunk(scr_a, 0, tid);
            cp_commit();

            for (int c = 0; c < 8; c++) {
                if (c < 7) {
                    stage_h_chunk(scr_a + ((c + 1) & 1) * HBUF_STRIDE_B, c + 1,
                                  tid);
                    cp_commit();
                    cp_wait<1>();
                } else {
                    cp_wait<0>();
                }
                __syncthreads();
                rec_compute(scr_a + (c & 1) * HBUF_STRIDE_B, wh_a, wl_a, c,
                            ks, ch, lane, acc);
                __syncthreads();
            }
        } else {
            __syncthreads();
        }

        // partials -> red (aliases h staging; compute synced above)
        write_partials(red, wid, lane, acc);
        __syncthreads();

        // reduce 8 partials per col-half; thread (b = tid&31, cp = tid>>5)
        {
            int b = tid & 31;
            int cp = tid >> 5;               // 0..15 -> cols 2cp, 2cp+1
            int half = cp >> 3;              // col half
            float2 s = make_float2(0.0f, 0.0f);
            for (int w = 0; w < 8; w++) {
                float2 v = *(float2*)&red[(half * 8 + w) * 576 + b * 18 +
                                          ((cp * 2) & 15)];
                s.x += v.x;
                s.y += v.y;
            }
            gb[(cp * 2) * 34 + b] = s.x;
            gb[(cp * 2 + 1) * 34 + b] = s.y;
        }
        __syncthreads();

        // epilogue: thread (b, jj); c in register; write h fp32 + split bf16
        if (tid < 256) {
            const int b = tid >> 3;
            const int jj = tid & 7;
            float gate[4];
            for (int g = 0; g < 4; g++) {
                int col = g * 8 + jj;
                gate[g] = gb[col * 34 + b] + xb[b * 36 + col];
            }
            float ig = sigmoidf_(gate[0]);
            float fg = sigmoidf_(gate[1]);
            float gg = tanh_fast(gate[2]);
            float og = sigmoidf_(gate[3]);
            c_reg = fg * c_reg + ig * gg;
            float h = og * tanh_fast(c_reg);
            out[((size_t)b * NT + t) * NH + base + jj] = h;
            __nv_bfloat16 hh = __float2bfloat16(h);
            g_hh[b * NH + base + jj] = hh;
            g_hl[b * NH + base + jj] =
                __float2bfloat16(h - __bfloat162float(hh));
            if (write_final && t == NT - 1) {
                out[HSEQ + (size_t)b * NH + base + jj] = h;
                out[HSEQ + (size_t)(NB * NH) + (size_t)b * NH + base + jj] = c_reg;
            }
        }

        // grid barrier (skip after last step)
        if (t < NT - 1) {
            __threadfence();
            __syncthreads();
            bar_tgt += NCTA;
            if (tid == 0) {
                atomicAdd(&g_barrier, 1u);
                while (ld_acq(&g_barrier) < bar_tgt) { }
            }
            __syncthreads();
        }
    }
}

// ---------------------------------------------------------------------------
// launch
// ---------------------------------------------------------------------------
extern "C" void kernel_launch(void* const* d_in, const int* in_sizes, int n_in,
                              void* d_out, int out_size) {
    const float* x = (const float*)d_in[0];
    const float* wih = (const float*)d_in[1];
    const float* whh = (const float*)d_in[2];
    const float* bias = (const float*)d_in[3];
    float* out = (float*)d_out;

    (void)in_sizes;
    (void)n_in;

    cudaFuncSetAttribute(lstm_persist,
                         cudaFuncAttributeMaxDynamicSharedMemorySize,
                         PERSIST_SMEM);
    cudaFuncSetAttribute(mma_xproj,
                         cudaFuncAttributeMaxDynamicSharedMemorySize,
                         GEMM_SMEM);

    init_bar_kernel<<<1, 32>>>();

    split_kernel<<<(MTOT * ND) / 256, 256>>>(x, wih);

    dim3 grid(NG / 128, MTOT / 128);
    mma_xproj<<<grid, 256, GEMM_SMEM>>>(bias);

    int wf = (out_size >= (int)(HSEQ + 2 * NB * NH)) ? 1 : 0;
    lstm_persist<<<NCTA, NTHR, PERSIST_SMEM>>>(whh, out, wf);
}